// round 5
// baseline (speedup 1.0000x reference)
#include <cuda_runtime.h>
#include <cuda_bf16.h>

// ---------------- problem constants ----------------
#define ZD 21
#define YD 256
#define XD 256
#define BD 2
#define CIN 16
#define C1 32
#define C2 64
#define GRID_SZ (BD * ZD * YD * XD)   // 2,752,512
#define N_MAX 400000
#define BN_EPS 1e-3f

// ---------------- device scratch (no allocations allowed) ----------------
__device__ int   g_grid[GRID_SZ];          // dense hash: linear coord -> row idx (or -1)
__device__ float g_f1[N_MAX * C1];         // intermediate features after conv1+BN+ReLU

// ---------------- kernels ----------------
__global__ void reset_grid_kernel() {
    int i = blockIdx.x * blockDim.x + threadIdx.x;
    if (i < GRID_SZ) g_grid[i] = -1;
}

__global__ void scatter_kernel(const int* __restrict__ coors, int n) {
    int i = blockIdx.x * blockDim.x + threadIdx.x;
    if (i >= n) return;
    int4 c = ((const int4*)coors)[i];
    int lin = ((c.x * ZD + c.y) * YD + c.z) * XD + c.w;
    g_grid[lin] = i;
}

__device__ __forceinline__ float bn_relu(float x, float g, float b, float m, float v) {
    float r = (x - m) * (g * rsqrtf(v + BN_EPS)) + b;
    return r > 0.0f ? r : 0.0f;
}

// SubMConv3d: k=3, pad=1, outputs at input sites. 8 threads per voxel,
// each thread computes 4 output channels (float4).
__global__ void conv1_kernel(const float* __restrict__ feat,
                             const int*   __restrict__ coors,
                             const float* __restrict__ W1,
                             const float* __restrict__ g1,
                             const float* __restrict__ b1,
                             const float* __restrict__ m1,
                             const float* __restrict__ v1,
                             int n) {
    int tid = blockIdx.x * blockDim.x + threadIdx.x;
    int i = tid >> 3;
    int g = tid & 7;          // channel group: channels [4g, 4g+4)
    if (i >= n) return;

    int4 c = ((const int4*)coors)[i];
    int b = c.x, z = c.y, y = c.z, x = c.w;

    float4 acc = make_float4(0.f, 0.f, 0.f, 0.f);
    const float4* W4 = (const float4*)W1;   // layout [27][16][8 float4]

    #pragma unroll
    for (int dz = -1; dz <= 1; dz++) {
        int zz = z + dz;
        if (zz < 0 || zz >= ZD) continue;
        #pragma unroll
        for (int dy = -1; dy <= 1; dy++) {
            int yy = y + dy;
            if (yy < 0 || yy >= YD) continue;
            #pragma unroll
            for (int dx = -1; dx <= 1; dx++) {
                int xx = x + dx;
                if (xx < 0 || xx >= XD) continue;
                int lin = ((b * ZD + zz) * YD + yy) * XD + xx;
                int idx = g_grid[lin];
                if (idx < 0) continue;
                int k = (dz + 1) * 9 + (dy + 1) * 3 + (dx + 1);
                const float*  row = feat + idx * CIN;
                const float4* w   = W4 + (k * CIN) * 8 + g;  // + c*8 per channel
                #pragma unroll
                for (int cc = 0; cc < CIN; cc++) {
                    float  fv = __ldg(row + cc);
                    float4 wv = __ldg(w + cc * 8);
                    acc.x = fmaf(fv, wv.x, acc.x);
                    acc.y = fmaf(fv, wv.y, acc.y);
                    acc.z = fmaf(fv, wv.z, acc.z);
                    acc.w = fmaf(fv, wv.w, acc.w);
                }
            }
        }
    }

    int co = 4 * g;
    float4 o;
    o.x = bn_relu(acc.x, g1[co + 0], b1[co + 0], m1[co + 0], v1[co + 0]);
    o.y = bn_relu(acc.y, g1[co + 1], b1[co + 1], m1[co + 1], v1[co + 1]);
    o.z = bn_relu(acc.z, g1[co + 2], b1[co + 2], m1[co + 2], v1[co + 2]);
    o.w = bn_relu(acc.w, g1[co + 3], b1[co + 3], m1[co + 3], v1[co + 3]);
    ((float4*)(g_f1 + i * C1))[g] = o;
}

// SparseConv3d: k=3, s=2, pad=(0,1,1). 16 threads per output voxel,
// each thread computes 4 output channels.
__global__ void conv2_kernel(const int*   __restrict__ ocoors,
                             const float* __restrict__ W2,
                             const float* __restrict__ g2,
                             const float* __restrict__ b2,
                             const float* __restrict__ m2,
                             const float* __restrict__ v2,
                             float*       __restrict__ out,
                             int m) {
    int tid = blockIdx.x * blockDim.x + threadIdx.x;
    int i = tid >> 4;
    int g = tid & 15;         // channels [4g, 4g+4)
    if (i >= m) return;

    int4 c = ((const int4*)ocoors)[i];
    int b = c.x, oz = c.y, oy = c.z, ox = c.w;

    float4 acc = make_float4(0.f, 0.f, 0.f, 0.f);
    const float4* W4 = (const float4*)W2;   // layout [27][32][16 float4]

    #pragma unroll
    for (int jz = 0; jz < 3; jz++) {
        int zz = oz * 2 + jz;               // pad 0 in z
        if (zz >= ZD) continue;
        #pragma unroll
        for (int jy = 0; jy < 3; jy++) {
            int yy = oy * 2 - 1 + jy;       // pad 1 in y
            if (yy < 0 || yy >= YD) continue;
            #pragma unroll
            for (int jx = 0; jx < 3; jx++) {
                int xx = ox * 2 - 1 + jx;   // pad 1 in x
                if (xx < 0 || xx >= XD) continue;
                int lin = ((b * ZD + zz) * YD + yy) * XD + xx;
                int idx = g_grid[lin];
                if (idx < 0) continue;
                int k = jz * 9 + jy * 3 + jx;
                const float*  row = g_f1 + idx * C1;
                const float4* w   = W4 + (k * C1) * 16 + g;
                #pragma unroll
                for (int cc = 0; cc < C1; cc++) {
                    float  fv = __ldg(row + cc);
                    float4 wv = __ldg(w + cc * 16);
                    acc.x = fmaf(fv, wv.x, acc.x);
                    acc.y = fmaf(fv, wv.y, acc.y);
                    acc.z = fmaf(fv, wv.z, acc.z);
                    acc.w = fmaf(fv, wv.w, acc.w);
                }
            }
        }
    }

    int co = 4 * g;
    float4 o;
    o.x = bn_relu(acc.x, g2[co + 0], b2[co + 0], m2[co + 0], v2[co + 0]);
    o.y = bn_relu(acc.y, g2[co + 1], b2[co + 1], m2[co + 1], v2[co + 1]);
    o.z = bn_relu(acc.z, g2[co + 2], b2[co + 2], m2[co + 2], v2[co + 2]);
    o.w = bn_relu(acc.w, g2[co + 3], b2[co + 3], m2[co + 3], v2[co + 3]);
    ((float4*)(out + i * C2))[g] = o;
}

// Optional tail: if the harness flattens the full (f2, out_coors, batch_size)
// tuple into d_out, append out_coors (as float) and batch_size.
__global__ void tail_kernel(const int* __restrict__ ocoors,
                            const int* __restrict__ bs,
                            float* __restrict__ out,
                            int m, int extra) {
    int i = blockIdx.x * blockDim.x + threadIdx.x;
    if (i >= extra) return;
    float v;
    if (i < 4 * m)           v = (float)ocoors[i];
    else if (i == 4 * m)     v = (float)bs[0];
    else                     v = 0.0f;
    out[m * C2 + i] = v;
}

// ---------------- launch ----------------
extern "C" void kernel_launch(void* const* d_in, const int* in_sizes, int n_in,
                              void* d_out, int out_size) {
    const float* voxel_feat = (const float*)d_in[0];
    const int*   coors      = (const int*)  d_in[1];
    const int*   out_coors  = (const int*)  d_in[2];
    const float* W1 = (const float*)d_in[3];
    const float* g1 = (const float*)d_in[4];
    const float* b1 = (const float*)d_in[5];
    const float* m1 = (const float*)d_in[6];
    const float* v1 = (const float*)d_in[7];
    const float* W2 = (const float*)d_in[8];
    const float* g2 = (const float*)d_in[9];
    const float* b2 = (const float*)d_in[10];
    const float* m2 = (const float*)d_in[11];
    const float* v2 = (const float*)d_in[12];
    const int*   bs = (n_in > 13) ? (const int*)d_in[13] : nullptr;

    int n = in_sizes[0] / CIN;      // active input voxels
    int m = in_sizes[2] / 4;        // active output voxels
    float* out = (float*)d_out;

    reset_grid_kernel<<<(GRID_SZ + 255) / 256, 256>>>();
    scatter_kernel<<<(n + 255) / 256, 256>>>(coors, n);
    conv1_kernel<<<(n * 8 + 255) / 256, 256>>>(voxel_feat, coors, W1, g1, b1, m1, v1, n);
    conv2_kernel<<<(m * 16 + 255) / 256, 256>>>(out_coors, W2, g2, b2, m2, v2, out, m);

    int extra = out_size - m * C2;
    if (extra > 0 && bs != nullptr) {
        tail_kernel<<<(extra + 255) / 256, 256>>>(out_coors, bs, out, m, extra);
    }
}

// round 6
// speedup vs baseline: 2.7801x; 2.7801x over previous
#include <cuda_runtime.h>
#include <cuda_bf16.h>

// ---------------- problem constants ----------------
#define ZD 21
#define YD 256
#define XD 256
#define BD 2
#define CIN 16
#define C1 32
#define C2 64
#define GRID_SZ (BD * ZD * YD * XD)   // 2,752,512
#define N_MAX 400000
#define BN_EPS 1e-3f

// ---------------- device scratch ----------------
__device__ int   g_grid[GRID_SZ];          // dense hash: linear coord -> row idx (or -1)
__device__ float g_f1[N_MAX * C1];         // features after conv1+BN+ReLU

// ---------------- helper ----------------
__device__ __forceinline__ float bn_relu(float x, float g, float b, float m, float v) {
    float r = (x - m) * (g * rsqrtf(v + BN_EPS)) + b;
    return r > 0.0f ? r : 0.0f;
}

__global__ void reset_grid_kernel() {
    int i = blockIdx.x * blockDim.x + threadIdx.x;
    if (i < GRID_SZ) g_grid[i] = -1;
}

__global__ void scatter_kernel(const int* __restrict__ coors, int n) {
    int i = blockIdx.x * blockDim.x + threadIdx.x;
    if (i >= n) return;
    int4 c = ((const int4*)coors)[i];
    int lin = ((c.x * ZD + c.y) * YD + c.z) * XD + c.w;
    g_grid[lin] = i;
}

// ===================== conv1: SubMConv3d k=3 pad=1, CIN=16 -> C1=32 =====================
// One warp per voxel. Lane l computes output channel l.
// Lanes 0..26 do the 27 neighbor grid lookups in ONE warp LDG; then a
// ballot/ffs loop over active neighbors with warp-uniform control flow.
__global__ void conv1_kernel(const float* __restrict__ feat,
                             const int*   __restrict__ coors,
                             const float* __restrict__ W1,
                             const float* __restrict__ g1,
                             const float* __restrict__ b1,
                             const float* __restrict__ m1,
                             const float* __restrict__ v1,
                             int n) {
    int warp = blockIdx.x * (blockDim.x >> 5) + (threadIdx.x >> 5);
    int lane = threadIdx.x & 31;
    if (warp >= n) return;

    int4 c = ((const int4*)coors)[warp];   // uniform load (same addr across warp)

    // --- phase A: 27 neighbor lookups, one lane each ---
    int idx = -1;
    if (lane < 27) {
        int dz = lane / 9 - 1;
        int dy = (lane / 3) % 3 - 1;
        int dx = lane % 3 - 1;
        int zz = c.y + dz, yy = c.z + dy, xx = c.w + dx;
        if (zz >= 0 && zz < ZD && yy >= 0 && yy < YD && xx >= 0 && xx < XD) {
            int lin = ((c.x * ZD + zz) * YD + yy) * XD + xx;
            idx = g_grid[lin];
        }
    }
    unsigned mask = __ballot_sync(0xffffffffu, idx >= 0);

    // --- phase B: accumulate over active neighbors (warp-uniform loop) ---
    float acc = 0.0f;
    while (mask) {
        int k = __ffs(mask) - 1;
        mask &= mask - 1;
        int row = __shfl_sync(0xffffffffu, idx, k);

        const float4* f4 = (const float4*)(feat + row * CIN);
        float4 fa = __ldg(f4 + 0);
        float4 fb = __ldg(f4 + 1);
        float4 fc = __ldg(f4 + 2);
        float4 fd = __ldg(f4 + 3);
        float fv[16] = { fa.x, fa.y, fa.z, fa.w,
                         fb.x, fb.y, fb.z, fb.w,
                         fc.x, fc.y, fc.z, fc.w,
                         fd.x, fd.y, fd.z, fd.w };

        const float* wp = W1 + k * (CIN * C1) + lane;  // lane-contiguous per cc
        float wv[16];
        #pragma unroll
        for (int cc = 0; cc < CIN; cc++) wv[cc] = __ldg(wp + cc * C1);
        #pragma unroll
        for (int cc = 0; cc < CIN; cc++) acc = fmaf(fv[cc], wv[cc], acc);
    }

    float o = bn_relu(acc, __ldg(g1 + lane), __ldg(b1 + lane),
                      __ldg(m1 + lane), __ldg(v1 + lane));
    g_f1[warp * C1 + lane] = o;     // coalesced 128B store
}

// ===================== conv2: SparseConv3d k=3 s=2 pad=(0,1,1), C1=32 -> C2=64 =========
// One warp per output voxel. Lane l computes channels {2l, 2l+1} (float2 weights).
__global__ void conv2_kernel(const int*   __restrict__ ocoors,
                             const float* __restrict__ W2,
                             const float* __restrict__ g2,
                             const float* __restrict__ b2,
                             const float* __restrict__ m2,
                             const float* __restrict__ v2,
                             float*       __restrict__ out,
                             int m) {
    int warp = blockIdx.x * (blockDim.x >> 5) + (threadIdx.x >> 5);
    int lane = threadIdx.x & 31;
    if (warp >= m) return;

    int4 c = ((const int4*)ocoors)[warp];

    // --- phase A: 27 lookups, one lane each ---
    int idx = -1;
    if (lane < 27) {
        int jz = lane / 9;
        int jy = (lane / 3) % 3;
        int jx = lane % 3;
        int zz = c.y * 2 + jz;          // pad 0 in z (zz >= 0 always)
        int yy = c.z * 2 - 1 + jy;      // pad 1 in y
        int xx = c.w * 2 - 1 + jx;      // pad 1 in x
        if (zz < ZD && yy >= 0 && yy < YD && xx >= 0 && xx < XD) {
            int lin = ((c.x * ZD + zz) * YD + yy) * XD + xx;
            idx = g_grid[lin];
        }
    }
    unsigned mask = __ballot_sync(0xffffffffu, idx >= 0);

    // --- phase B ---
    float accx = 0.0f, accy = 0.0f;
    while (mask) {
        int k = __ffs(mask) - 1;
        mask &= mask - 1;
        int row = __shfl_sync(0xffffffffu, idx, k);

        const float4* f4 = (const float4*)(g_f1 + row * C1);        // 32 floats
        const float2* wp = (const float2*)(W2 + k * (C1 * C2)) + lane; // + cc*32 f2

        #pragma unroll
        for (int c8 = 0; c8 < 4; c8++) {           // 8 input channels per chunk
            float4 fa = __ldg(f4 + 2 * c8 + 0);
            float4 fb = __ldg(f4 + 2 * c8 + 1);
            float fv[8] = { fa.x, fa.y, fa.z, fa.w, fb.x, fb.y, fb.z, fb.w };
            float2 wv[8];
            #pragma unroll
            for (int j = 0; j < 8; j++) wv[j] = __ldg(wp + (8 * c8 + j) * (C2 / 2));
            #pragma unroll
            for (int j = 0; j < 8; j++) {
                accx = fmaf(fv[j], wv[j].x, accx);
                accy = fmaf(fv[j], wv[j].y, accy);
            }
        }
    }

    float2 gg = __ldg((const float2*)g2 + lane);
    float2 bb = __ldg((const float2*)b2 + lane);
    float2 mm = __ldg((const float2*)m2 + lane);
    float2 vv = __ldg((const float2*)v2 + lane);
    float2 o;
    o.x = bn_relu(accx, gg.x, bb.x, mm.x, vv.x);
    o.y = bn_relu(accy, gg.y, bb.y, mm.y, vv.y);
    ((float2*)(out + warp * C2))[lane] = o;        // coalesced 256B store
}

// Optional tail: if the harness flattens (f2, out_coors, batch_size) into d_out.
__global__ void tail_kernel(const int* __restrict__ ocoors,
                            const int* __restrict__ bs,
                            float* __restrict__ out,
                            int m, int extra) {
    int i = blockIdx.x * blockDim.x + threadIdx.x;
    if (i >= extra) return;
    float v;
    if (i < 4 * m)           v = (float)ocoors[i];
    else if (i == 4 * m)     v = (float)bs[0];
    else                     v = 0.0f;
    out[m * C2 + i] = v;
}

// ---------------- launch ----------------
extern "C" void kernel_launch(void* const* d_in, const int* in_sizes, int n_in,
                              void* d_out, int out_size) {
    const float* voxel_feat = (const float*)d_in[0];
    const int*   coors      = (const int*)  d_in[1];
    const int*   out_coors  = (const int*)  d_in[2];
    const float* W1 = (const float*)d_in[3];
    const float* g1 = (const float*)d_in[4];
    const float* b1 = (const float*)d_in[5];
    const float* m1 = (const float*)d_in[6];
    const float* v1 = (const float*)d_in[7];
    const float* W2 = (const float*)d_in[8];
    const float* g2 = (const float*)d_in[9];
    const float* b2 = (const float*)d_in[10];
    const float* m2 = (const float*)d_in[11];
    const float* v2 = (const float*)d_in[12];
    const int*   bs = (n_in > 13) ? (const int*)d_in[13] : nullptr;

    int n = in_sizes[0] / CIN;      // active input voxels
    int m = in_sizes[2] / 4;        // active output voxels
    float* out = (float*)d_out;

    reset_grid_kernel<<<(GRID_SZ + 255) / 256, 256>>>();
    scatter_kernel<<<(n + 255) / 256, 256>>>(coors, n);

    // one warp per voxel, 8 warps (256 threads) per block
    conv1_kernel<<<(n + 7) / 8, 256>>>(voxel_feat, coors, W1, g1, b1, m1, v1, n);
    conv2_kernel<<<(m + 7) / 8, 256>>>(out_coors, W2, g2, b2, m2, v2, out, m);

    int extra = out_size - m * C2;
    if (extra > 0 && bs != nullptr) {
        tail_kernel<<<(extra + 255) / 256, 256>>>(out_coors, bs, out, m, extra);
    }
}